// round 16
// baseline (speedup 1.0000x reference)
#include <cuda_runtime.h>
#include <cuda_fp16.h>
#include <cstdint>
#include <cstddef>

// ---------------------------------------------------------------------------
// GraphSAGE 2-layer, GB300 sm_103a (base-PTX target: no tcgen05 available).
//   h1 = relu( segmean(x@W1l) + b1 + x@W1r )
//   out =      segmean(h1@W2l) + b2 + h1@W2r
// GEMMs fused as [K,256] = [W_l | W_r]; aggregation in projected 128-d space.
// GEMM1: fp16 mma.sync.m16n8k16, BK=64, one barrier/slice, CSR fill fused,
//        x via __ldcs (keeps fp16 lin L2-resident).
// Layer 2 FUSED: one kernel per 128-row tile gathers its own h1 rows (CSR
//        mean+bias+root+relu) into A-smem, then does the full K=128 MMA
//        against the whole 256x128 W2 tile in smem. h1 never touches DRAM;
//        gather latency hides under B-loads + other blocks' MMA.
// ---------------------------------------------------------------------------

#define MAXN 100000
#define MAXE 200000

// scratch (static device globals: allocation-free contract)
__device__ __half g_W1[256 * 384];            // n-major [256][384]
__device__ __half g_W2[256 * 128];            // n-major [256][128]
__device__ __half g_lin [(size_t)MAXN * 256]; // layer-1 GEMM output
__device__ __half g_lin2[(size_t)MAXN * 256]; // layer-2 fused output
__device__ int    g_src[MAXE];
__device__ int    g_dst[MAXE];
__device__ int    g_deg[MAXN];                // zeroed by scan_k after use
__device__ int    g_off[MAXN + 1];
__device__ int    g_cur[MAXN];
__device__ int    g_csr[MAXE];
__device__ int    g_look[128];                // lookback slots: agg+1, 0=not ready

__device__ __forceinline__ uint32_t smem_u32(const void* p) {
    uint32_t a;
    asm("{ .reg .u64 t; cvta.to.shared.u64 t, %1; cvt.u32.u64 %0, t; }"
        : "=r"(a) : "l"(p));
    return a;
}

__device__ __forceinline__ uint2 f4_to_h4(float4 v) {
    __half2 lo = __floats2half2_rn(v.x, v.y);
    __half2 hi = __floats2half2_rn(v.z, v.w);
    uint2 r;
    r.x = *reinterpret_cast<unsigned*>(&lo);
    r.y = *reinterpret_cast<unsigned*>(&hi);
    return r;
}

// ---------------- setup: edges (detect+normalize+degree) + weight pack -----
__global__ void setup_k(const void* __restrict__ ei, int E,
                        const float* __restrict__ W1l, const float* __restrict__ W1r,
                        const float* __restrict__ W2l, const float* __restrict__ W2r,
                        int PB) {
    if (blockIdx.x < PB) {
        __shared__ int s_bad;
        if (threadIdx.x == 0) s_bad = 0;
        __syncthreads();
        // int64 edges (nonneg, < 2^31) => all high words of first 64 entries 0
        const unsigned* w = (const unsigned*)ei;
        if (threadIdx.x < 64 && w[2 * threadIdx.x + 1] != 0u) s_bad = 1;
        __syncthreads();
        const int is64 = !s_bad;

        int gt = blockIdx.x * blockDim.x + threadIdx.x;
        if (gt < 128) g_look[gt] = 0;          // reset lookback slots each replay
        if (gt >= E) return;
        int s, d;
        if (is64) {
            const long long* p = (const long long*)ei;
            s = (int)p[gt];
            d = (int)p[E + gt];
        } else {
            const int* p = (const int*)ei;
            s = p[gt];
            d = p[E + gt];
        }
        g_src[gt] = s;
        g_dst[gt] = d;
        atomicAdd(g_deg + d, 1);
    } else {
        int idx = (blockIdx.x - PB) * blockDim.x + threadIdx.x;
        if (idx < 256 * 384) {
            int n = idx / 384, k = idx - n * 384;
            float v = (n < 128) ? W1l[k * 128 + n] : W1r[k * 128 + n - 128];
            g_W1[idx] = __float2half_rn(v);
        } else if (idx < 256 * 384 + 256 * 128) {
            int j = idx - 256 * 384;
            int n = j >> 7, k = j & 127;
            float v = (n < 128) ? W2l[k * 128 + n] : W2r[k * 128 + n - 128];
            g_W2[j] = __float2half_rn(v);
        }
    }
}

// ---------------- CSR offsets: single-pass windowed-lookback scan ----------
__global__ void scan_k(int M, int E) {
    __shared__ int wsum[8];
    __shared__ int sprefix;
    const int tid = threadIdx.x, lane = tid & 31, wid = tid >> 5;
    const int b = blockIdx.x;
    const int base = b * 1024 + tid * 4;

    int d[4], sum4 = 0;
#pragma unroll
    for (int i = 0; i < 4; i++) {
        int n = base + i;
        d[i] = (n < M) ? g_deg[n] : 0;
        sum4 += d[i];
    }
    int t = sum4;
#pragma unroll
    for (int o = 1; o < 32; o <<= 1) {
        int v = __shfl_up_sync(0xFFFFFFFFu, t, o);
        if (lane >= o) t += v;
    }
    if (lane == 31) wsum[wid] = t;
    __syncthreads();
    if (tid < 8) {
        int wv = wsum[tid];
#pragma unroll
        for (int o = 1; o < 8; o <<= 1) {
            int v = __shfl_up_sync(0xFFu, wv, o);
            if (tid >= o) wv += v;
        }
        wsum[tid] = wv;
    }
    __syncthreads();

    if (tid == 0) *((volatile int*)&g_look[b]) = wsum[7] + 1;

    if (wid == 0) {
        int pre = 0;
        for (int s0 = 0; s0 < b; s0 += 32) {
            int i = s0 + lane, v = 0;
            if (i < b) {
                volatile int* p = &g_look[i];
                do { v = *p; } while (v == 0);
                v -= 1;
            }
            pre += v;
        }
#pragma unroll
        for (int o = 16; o > 0; o >>= 1) pre += __shfl_xor_sync(0xFFFFFFFFu, pre, o);
        if (lane == 0) sprefix = pre;
    }
    __syncthreads();

    int run = sprefix + (t - sum4) + (wid > 0 ? wsum[wid - 1] : 0);
#pragma unroll
    for (int i = 0; i < 4; i++) {
        int n = base + i;
        if (n < M) { g_off[n] = run; g_cur[n] = run; g_deg[n] = 0; run += d[i]; }
    }
    if (b == 0 && tid == 0) g_off[M] = E;
}

// ---------------- final gather: mean + bias + root, fp32 out ---------------
#define NPW 4
__global__ void gather_out_k(const __half* __restrict__ lin, const float* __restrict__ bias,
                             float* __restrict__ out, int M) {
    const int warpId = (blockIdx.x * blockDim.x + threadIdx.x) >> 5;
    const int lane = threadIdx.x & 31;
    const int half = lane >> 4, hl = lane & 15;
    const unsigned hoff = hl * 8u;

    float4 b0 = *(const float4*)(bias + hl * 8);
    float4 b1 = *(const float4*)(bias + hl * 8 + 4);

    int n0 = warpId * NPW;
#pragma unroll
    for (int ni = 0; ni < NPW; ni++) {
        int node = n0 + ni;
        if (node >= M) return;
        int e0 = g_off[node], e1 = g_off[node + 1];

        float a[8] = {0.f, 0.f, 0.f, 0.f, 0.f, 0.f, 0.f, 0.f};
        int e = e0 + half;
        int s = (e < e1) ? g_csr[e] : -1;
        while (s >= 0) {
            int e2 = e + 2;
            int snext = (e2 < e1) ? g_csr[e2] : -1;
            uint4 u = *(const uint4*)(lin + ((unsigned)s << 8) + hoff);
            const __half2* h = (const __half2*)&u;
#pragma unroll
            for (int i = 0; i < 4; i++) {
                float2 f = __half22float2(h[i]);
                a[2 * i] += f.x;
                a[2 * i + 1] += f.y;
            }
            s = snext;
            e = e2;
        }
#pragma unroll
        for (int i = 0; i < 8; i++)
            a[i] += __shfl_down_sync(0xFFFFFFFFu, a[i], 16);

        if (half == 0) {
            float inv = 1.0f / fmaxf((float)(e1 - e0), 1.0f);
            uint4 ru = *(const uint4*)(lin + ((unsigned)node << 8) + 128u + hoff);
            const __half2* rh = (const __half2*)&ru;
            const float bb[8] = {b0.x, b0.y, b0.z, b0.w, b1.x, b1.y, b1.z, b1.w};
            float o[8];
#pragma unroll
            for (int i = 0; i < 4; i++) {
                float2 rf = __half22float2(rh[i]);
                o[2 * i]     = fmaf(a[2 * i],     inv, bb[2 * i])     + rf.x;
                o[2 * i + 1] = fmaf(a[2 * i + 1], inv, bb[2 * i + 1]) + rf.y;
            }
            float* dst = out + ((unsigned)node << 7) + hoff;
            __stcs((float4*)dst,       make_float4(o[0], o[1], o[2], o[3]));
            __stcs((float4*)(dst + 4), make_float4(o[4], o[5], o[6], o[7]));
        }
    }
}

// ---------------- GEMM1: C[M,256] = fp16(A[M,384]) @ W1^T ------------------
// 1-D grid: first nFill blocks do the CSR bucket fill, rest GEMM tiles.
static constexpr int GEMM_BUF = 128 * 72 * 2;
static constexpr int GEMM_SMEM = 4 * GEMM_BUF;          // 73728 B

__global__ __launch_bounds__(256, 2) void gemm1_k(
    const float* __restrict__ A32, const __half* __restrict__ W,
    __half* __restrict__ C, int M, int K, int nFill, int E)
{
    const int tid = threadIdx.x;
    if ((int)blockIdx.x < nFill) {          // fused CSR fill
        int e = blockIdx.x * 256 + tid;
        if (e < E) {
            int pos = atomicAdd(g_cur + g_dst[e], 1);
            g_csr[pos] = g_src[e];
        }
        return;
    }
    const int bid = blockIdx.x - nFill;

    extern __shared__ __align__(16) char smem[];
    __half (*As)[72] = (__half(*)[72])smem;
    __half (*Bs)[72] = (__half(*)[72])(smem + 2 * GEMM_BUF);

    const int warp = tid >> 5, lane = tid & 31;
    const int wm = warp >> 1, wn = warp & 1;
    const int g = lane >> 2, tg = lane & 3;
    const int colBlock = (bid & 1) * 128;
    const int rowBlock = (bid >> 1) * 128;

    float acc[2][8][4];
#pragma unroll
    for (int i = 0; i < 2; i++)
#pragma unroll
        for (int j = 0; j < 8; j++)
#pragma unroll
            for (int k = 0; k < 4; k++) acc[i][j][k] = 0.f;

    const int NT = K >> 6;

    const uint32_t asb = smem_u32(&As[0][0]);
    const uint32_t bsb = smem_u32(&Bs[0][0]);
    const uint32_t aoff = ((wm * 32 + (lane & 15)) * 72 + (lane >> 4) * 8) * 2;
    const uint32_t boff = ((wn * 64 + ((lane >> 4) * 8) + (lane & 7)) * 72
                           + ((lane >> 3) & 1) * 8) * 2;

    auto stage = [&](int buf, int k0) {
#pragma unroll
        for (int i = 0; i < 8; i++) {
            int u = tid + (i << 8);
            int row = u >> 4, q = u & 15;
            int gr = rowBlock + row;
            float4 v = make_float4(0.f, 0.f, 0.f, 0.f);
            if (gr < M) v = __ldcs((const float4*)(A32 + (size_t)gr * K + k0 + q * 4));
            *(uint2*)(&As[(buf << 7) + row][q * 4]) = f4_to_h4(v);
        }
#pragma unroll
        for (int i = 0; i < 8; i++) {
            int u = tid + (i << 8);
            int row = u >> 4, q = u & 15;
            *(uint2*)(&Bs[(buf << 7) + row][q * 4]) =
                *(const uint2*)(W + (size_t)(colBlock + row) * K + k0 + q * 4);
        }
    };

    stage(0, 0);
    __syncthreads();

    for (int kt = 0; kt < NT; kt++) {
        const int cur = kt & 1;
        if (kt + 1 < NT) stage(cur ^ 1, (kt + 1) << 6);

        const uint32_t abase = asb + cur * 18432;
        const uint32_t bbase = bsb + cur * 18432;
#pragma unroll
        for (int ks = 0; ks < 4; ks++) {
            unsigned a[2][4];
#pragma unroll
            for (int mt = 0; mt < 2; mt++) {
                uint32_t addr = abase + aoff + mt * 2304 + ks * 32;
                asm volatile(
                    "ldmatrix.sync.aligned.m8n8.x4.shared.b16 {%0,%1,%2,%3}, [%4];"
                    : "=r"(a[mt][0]), "=r"(a[mt][1]), "=r"(a[mt][2]), "=r"(a[mt][3])
                    : "r"(addr));
            }
            unsigned b[8][2];
#pragma unroll
            for (int p = 0; p < 4; p++) {
                uint32_t addr = bbase + boff + p * 2304 + ks * 32;
                asm volatile(
                    "ldmatrix.sync.aligned.m8n8.x4.shared.b16 {%0,%1,%2,%3}, [%4];"
                    : "=r"(b[2 * p][0]), "=r"(b[2 * p][1]),
                      "=r"(b[2 * p + 1][0]), "=r"(b[2 * p + 1][1])
                    : "r"(addr));
            }
#pragma unroll
            for (int mt = 0; mt < 2; mt++)
#pragma unroll
                for (int nt = 0; nt < 8; nt++) {
                    asm volatile(
                        "mma.sync.aligned.m16n8k16.row.col.f32.f16.f16.f32 "
                        "{%0,%1,%2,%3}, {%4,%5,%6,%7}, {%8,%9}, {%0,%1,%2,%3};\n"
                        : "+f"(acc[mt][nt][0]), "+f"(acc[mt][nt][1]),
                          "+f"(acc[mt][nt][2]), "+f"(acc[mt][nt][3])
                        : "r"(a[mt][0]), "r"(a[mt][1]), "r"(a[mt][2]), "r"(a[mt][3]),
                          "r"(b[nt][0]), "r"(b[nt][1]));
                }
        }
        __syncthreads();
    }

#pragma unroll
    for (int mt = 0; mt < 2; mt++)
#pragma unroll
        for (int nt = 0; nt < 8; nt++) {
            int row0 = rowBlock + wm * 32 + mt * 16 + g;
            int col  = colBlock + wn * 64 + nt * 8 + tg * 2;
            if (row0 < M)
                *(__half2*)(C + (size_t)row0 * 256 + col) =
                    __floats2half2_rn(acc[mt][nt][0], acc[mt][nt][1]);
            int row1 = row0 + 8;
            if (row1 < M)
                *(__half2*)(C + (size_t)row1 * 256 + col) =
                    __floats2half2_rn(acc[mt][nt][2], acc[mt][nt][3]);
        }
}

// ---------------- FUSED layer 2: gather h1 tile + full-K GEMM --------------
// One block = 128 rows x 256 cols, K=128 entirely in smem (no K-pipeline).
// 512 threads / 16 warps: warp grid 4x4, warp tile 32x64.
// Phase 1: issue W2 tile loads (64KB) + per-warp gather of 8 h1 rows
//          (CSR mean + b1 + root + relu) straight into A-smem as fp16.
// Phase 2: one barrier, then 8 k16 MMA steps, epilogue -> lin2.
// Row stride 136 halfs (272B): rows shift 16B mod 128B -> LDSM conflict-free.
static constexpr int F_STRIDE = 136;
static constexpr int F_AB = 128 * F_STRIDE * 2;               // 34816 B
static constexpr int F_SMEM = F_AB + 256 * F_STRIDE * 2;      // 104448 B

__global__ __launch_bounds__(512, 1) void gemm2_fused_k(
    const __half* __restrict__ lin1, const __half* __restrict__ W,
    const float* __restrict__ bias, __half* __restrict__ C, int M)
{
    extern __shared__ __align__(16) char smem[];
    __half (*As)[F_STRIDE] = (__half(*)[F_STRIDE])smem;
    __half (*Bs)[F_STRIDE] = (__half(*)[F_STRIDE])(smem + F_AB);

    const int tid = threadIdx.x;
    const int warp = tid >> 5, lane = tid & 31;
    const int rowBlock = blockIdx.x << 7;

    // B tile: W2 [256][128] -> smem (independent loads, overlap with gather)
#pragma unroll
    for (int i = 0; i < 8; i++) {
        int u = tid + (i << 9);
        int row = u >> 4, q = u & 15;
        *(uint4*)(&Bs[row][q * 8]) = *(const uint4*)(W + row * 128 + q * 8);
    }

    // gather this block's 128 h1 rows: warp w -> local rows [8w, 8w+8)
    const int half = lane >> 4, hl = lane & 15;
    const unsigned hoff = hl * 8u;
    float4 b0 = *(const float4*)(bias + hl * 8);
    float4 b1v = *(const float4*)(bias + hl * 8 + 4);
    const float bb[8] = {b0.x, b0.y, b0.z, b0.w, b1v.x, b1v.y, b1v.z, b1v.w};

#pragma unroll
    for (int ni = 0; ni < 8; ni++) {
        int lr = (warp << 3) + ni;
        int node = rowBlock + lr;
        float a[8] = {0.f, 0.f, 0.f, 0.f, 0.f, 0.f, 0.f, 0.f};
        int deg = 0;
        if (node < M) {
            int e0 = g_off[node], e1 = g_off[node + 1];
            deg = e1 - e0;
            int e = e0 + half;
            int s = (e < e1) ? g_csr[e] : -1;
            while (s >= 0) {
                int e2 = e + 2;
                int snext = (e2 < e1) ? g_csr[e2] : -1;
                uint4 u = *(const uint4*)(lin1 + ((unsigned)s << 8) + hoff);
                const __half2* h = (const __half2*)&u;
#pragma unroll
                for (int i = 0; i < 4; i++) {
                    float2 f = __half22float2(h[i]);
                    a[2 * i] += f.x;
                    a[2 * i + 1] += f.y;
                }
                s = snext;
                e = e2;
            }
        }
#pragma unroll
        for (int i = 0; i < 8; i++)
            a[i] += __shfl_down_sync(0xFFFFFFFFu, a[i], 16);

        if (half == 0) {
            uint4 w = make_uint4(0u, 0u, 0u, 0u);
            if (node < M) {
                float inv = 1.0f / fmaxf((float)deg, 1.0f);
                uint4 ru = *(const uint4*)(lin1 + ((unsigned)node << 8) + 128u + hoff);
                const __half2* rh = (const __half2*)&ru;
                unsigned* wp = (unsigned*)&w;
#pragma unroll
                for (int i = 0; i < 4; i++) {
                    float2 rf = __half22float2(rh[i]);
                    float ox = fmaxf(fmaf(a[2 * i],     inv, bb[2 * i])     + rf.x, 0.f);
                    float oy = fmaxf(fmaf(a[2 * i + 1], inv, bb[2 * i + 1]) + rf.y, 0.f);
                    __half2 hh = __floats2half2_rn(ox, oy);
                    wp[i] = *reinterpret_cast<unsigned*>(&hh);
                }
            }
            *(uint4*)(&As[lr][hoff]) = w;
        }
    }
    __syncthreads();

    // MMA: warp grid 4x4 (wm rows x wn cols), warp tile 32x64, K=128
    const int wm = warp >> 2, wn = warp & 3;
    const int g = lane >> 2, tg = lane & 3;
    const uint32_t asb = smem_u32(&As[0][0]);
    const uint32_t bsb = smem_u32(&Bs[0][0]);
    const uint32_t aoff = ((wm * 32 + (lane & 15)) * F_STRIDE + (lane >> 4) * 8) * 2;
    const uint32_t boff = ((wn * 64 + ((lane >> 4) * 8) + (lane & 7)) * F_STRIDE
                           + ((lane >> 3) & 1) * 8) * 2;

    float acc[2][8][4];
#pragma unroll
    for (int i = 0; i < 2; i++)
#pragma unroll
        for (int j = 0; j < 8; j++)
#pragma unroll
            for (int k = 0; k < 4; k++) acc[i][j][k] = 0.f;

#pragma unroll
    for (int ks = 0; ks < 8; ks++) {
        unsigned a[2][4];
#pragma unroll
        for (int mt = 0; mt < 2; mt++) {
            uint32_t addr = asb + aoff + mt * (16 * F_STRIDE * 2) + ks * 32;
            asm volatile(
                "ldmatrix.sync.aligned.m8n8.x4.shared.b16 {%0,%1,%2,%3}, [%4];"
                : "=r"(a[mt][0]), "=r"(a[mt][1]), "=r"(a[mt][2]), "=r"(a[mt][3])
                : "r"(addr));
        }
        unsigned b[8][2];
#pragma unroll
        for (int p = 0; p < 4; p++) {
            uint32_t addr = bsb + boff + p * (16 * F_STRIDE * 2) + ks * 32;
            asm volatile(
                "ldmatrix.sync.aligned.m8n8.x4.shared.b16 {%0,%1,%2,%3}, [%4];"
                : "=r"(b[2 * p][0]), "=r"(b[2 * p][1]),
                  "=r"(b[2 * p + 1][0]), "=r"(b[2 * p + 1][1])
                : "r"(addr));
        }
#pragma unroll
        for (int mt = 0; mt < 2; mt++)
#pragma unroll
            for (int nt = 0; nt < 8; nt++) {
                asm volatile(
                    "mma.sync.aligned.m16n8k16.row.col.f32.f16.f16.f32 "
                    "{%0,%1,%2,%3}, {%4,%5,%6,%7}, {%8,%9}, {%0,%1,%2,%3};\n"
                    : "+f"(acc[mt][nt][0]), "+f"(acc[mt][nt][1]),
                      "+f"(acc[mt][nt][2]), "+f"(acc[mt][nt][3])
                    : "r"(a[mt][0]), "r"(a[mt][1]), "r"(a[mt][2]), "r"(a[mt][3]),
                      "r"(b[nt][0]), "r"(b[nt][1]));
            }
    }

    // epilogue -> lin2, fp16
#pragma unroll
    for (int mt = 0; mt < 2; mt++)
#pragma unroll
        for (int nt = 0; nt < 8; nt++) {
            int row0 = rowBlock + wm * 32 + mt * 16 + g;
            int col  = wn * 64 + nt * 8 + tg * 2;
            if (row0 < M)
                *(__half2*)(C + (size_t)row0 * 256 + col) =
                    __floats2half2_rn(acc[mt][nt][0], acc[mt][nt][1]);
            int row1 = row0 + 8;
            if (row1 < M)
                *(__half2*)(C + (size_t)row1 * 256 + col) =
                    __floats2half2_rn(acc[mt][nt][2], acc[mt][nt][3]);
        }
}

// ---------------------------------------------------------------------------
extern "C" void kernel_launch(void* const* d_in, const int* in_sizes, int n_in,
                              void* d_out, int out_size) {
    const float* x   = (const float*)d_in[0];
    const void*  ei  = d_in[1];
    const float* W1l = (const float*)d_in[2];
    const float* b1  = (const float*)d_in[3];
    const float* W1r = (const float*)d_in[4];
    const float* W2l = (const float*)d_in[5];
    const float* b2  = (const float*)d_in[6];
    const float* W2r = (const float*)d_in[7];
    float* out = (float*)d_out;

    const int M = in_sizes[0] / 384;
    const int E = in_sizes[1] / 2;
    const int NB = (M + 1023) / 1024;

    __half *pLin, *pLin2, *pW1, *pW2;
    cudaGetSymbolAddress((void**)&pLin, g_lin);
    cudaGetSymbolAddress((void**)&pLin2, g_lin2);
    cudaGetSymbolAddress((void**)&pW1, g_W1);
    cudaGetSymbolAddress((void**)&pW2, g_W2);

    cudaFuncSetAttribute(gemm1_k, cudaFuncAttributeMaxDynamicSharedMemorySize, GEMM_SMEM);
    cudaFuncSetAttribute(gemm2_fused_k, cudaFuncAttributeMaxDynamicSharedMemorySize, F_SMEM);

    const int T = 256;
    const int PB = (E + T - 1) / T;                         // prep/fill blocks
    const int WB = (256 * 384 + 256 * 128 + T - 1) / T;     // pack blocks
    const int RB = (M + 127) / 128;                         // row blocks
    const int gatherBlocks = (M + NPW * 8 - 1) / (NPW * 8);

    // setup: [edge prep + weight pack] -> [offset scan] (deg self-clears)
    setup_k<<<PB + WB, T>>>(ei, E, W1l, W1r, W2l, W2r, PB);
    scan_k<<<NB, T>>>(M, E);

    // layer 1 GEMM (CSR fill fused into launch)
    gemm1_k<<<PB + 2 * RB, T, GEMM_SMEM>>>(x, pW1, pLin, M, 384, PB, E);

    // layer 2: fused gather(h1) + GEMM  (reads lin, writes lin2)
    gemm2_fused_k<<<RB, 512, F_SMEM>>>(pLin, pW2, b1, pLin2, M);

    // final gather -> fp32 out
    gather_out_k<<<gatherBlocks, T>>>(pLin2, b2, out, M);
}